// round 15
// baseline (speedup 1.0000x reference)
#include <cuda_runtime.h>
#include <cuda_fp16.h>

// CapsuleLayer dynamic routing, GB300 sm_103a.
// B=64, I=2048, Din=16, J=32, D=32, 3 routing iters.
//
// uhat2: grid (j=32, itile=16). Block streams its 128 i's through an 8-stage
// cp.async ring (stage = 2KB W[j,i,:,:] contiguous + 4KB x[:,i,:]), computes
// u_hat fp16 -> g_U[b][i][j*32+d] (one STG.128 per lane per i) AND accumulates
// the iter-0 uniform-c sum s0 in registers (fixed i order, single writer per
// (itile,b,j,d) -> deterministic), writing g_spart[itile] directly.
// This DELETES the route0 streaming pass (256 MB re-read).
// Routes + squash: round-13 proven, unchanged.
// Sequence: uhat2, squash(0), route, squash(1), route, squash(2).

#define BB 64
#define II 2048
#define CC 16
#define JJ 32
#define DD 32
#define NTILE 16   // i-tiles
#define NSTAGE 5   // route ring stages (16KB each)
#define NITER 16   // route stages per block
#define NST 8      // uhat2 ring stages
#define STGB 6144  // uhat2 stage bytes: 2048 W + 4096 x
#define UITER 128  // uhat2 i per block

typedef unsigned long long u64;
typedef unsigned int u32;

__device__ __half g_U[(size_t)BB * II * JJ * DD];   // 256 MB scratch (fp16)
__device__ float g_osum[BB * JJ * DD];              // running output sum
__device__ float g_spart[NTILE][BB * JJ * DD];      // per-itile partial s

// ---------- packed fp32x2 helpers ----------
__device__ __forceinline__ u64 fma2(u64 a, u64 b, u64 c) {
    u64 d;
    asm("fma.rn.f32x2 %0, %1, %2, %3;" : "=l"(d) : "l"(a), "l"(b), "l"(c));
    return d;
}
__device__ __forceinline__ u64 add2(u64 a, u64 b) {
    u64 d;
    asm("add.rn.f32x2 %0, %1, %2;" : "=l"(d) : "l"(a), "l"(b));
    return d;
}
__device__ __forceinline__ float hsum2(u64 v) {
    float a, b;
    asm("mov.b64 {%0, %1}, %2;" : "=f"(a), "=f"(b) : "l"(v));
    return a + b;
}
// pack two fp32 -> fp16x2 in a u32 (round-to-nearest; == __floats2half2_rn)
__device__ __forceinline__ u32 cvtpack(float lo, float hi) {
    u32 h;
    asm("cvt.rn.f16x2.f32 %0, %1, %2;" : "=r"(h) : "f"(hi), "f"(lo));
    return h;
}

// ---------- cp.async helpers ----------
__device__ __forceinline__ void cpasync16(unsigned smem_addr, const void* g) {
    asm volatile("cp.async.cg.shared.global [%0], [%1], 16;" ::"r"(smem_addr),
                 "l"(g));
}
__device__ __forceinline__ void cpcommit() {
    asm volatile("cp.async.commit_group;");
}
template <int N>
__device__ __forceinline__ void cpwait() {
    asm volatile("cp.async.wait_group %0;" ::"n"(N));
}

// ---------------------------------------------------------------------------
// Kernel A (uhat2): u_hat[b][i][j*32+d] = sum_c W[j][i][d][c] * x[b][i][c]
// (fp16), plus s0[b,j,d] = (1/32) sum_i u_hat (fp32, register-accumulated).
// Block (j, itile): 128 i's via 8-stage ring. Thread: b = w*8+(l&7),
// q = l>>3 -> rows q*8..q*8+7. W LDS are 8-lane broadcasts (conflict-free).
// ---------------------------------------------------------------------------
__global__ void __launch_bounds__(256, 3)
uhat_kernel(const float* __restrict__ x, const float* __restrict__ W) {
    extern __shared__ __align__(16) char dsm[];
    const int j = blockIdx.x;      // 0..31
    const int itile = blockIdx.y;  // 0..15
    const int t = threadIdx.x;
    const int w = t >> 5, l = t & 31;
    const int b = w * 8 + (l & 7);
    const int q = l >> 3;
    const int i0 = itile * UITER;

    // W slice for (j,i) is 2048 contiguous bytes at ((j*II+i)*2048).
    const char* Wg =
        reinterpret_cast<const char*>(W) + ((size_t)j * II + i0) * 2048;
    const char* Xg = reinterpret_cast<const char*>(x);
    const unsigned sb0 = (unsigned)__cvta_generic_to_shared(dsm);

    // copy roles: t<128 -> W granule t; t>=128 -> x granules g, g+1.
    const int xg = (t - 128) * 2;
    const int xb0 = xg >> 2, xp0 = xg & 3;
    const int xb1 = (xg + 1) >> 2, xp1 = (xg + 1) & 3;

    // prologue: stages 0..NST-2
    #pragma unroll
    for (int s = 0; s < NST - 1; s++) {
        unsigned sb = sb0 + (unsigned)(s * STGB);
        if (t < 128) {
            cpasync16(sb + (unsigned)(t * 16), Wg + (size_t)s * 2048 + t * 16);
        } else {
            cpasync16(sb + (unsigned)(2048 + xg * 16),
                      Xg + ((size_t)xb0 * II + i0 + s) * 64 + xp0 * 16);
            cpasync16(sb + (unsigned)(2048 + xg * 16 + 16),
                      Xg + ((size_t)xb1 * II + i0 + s) * 64 + xp1 * 16);
        }
        cpcommit();
    }

    float s0[8];
    #pragma unroll
    for (int dd = 0; dd < 8; dd++) s0[dd] = 0.f;

    // output base: byte = b*II*2048 + i*2048 + j*64 + q*16
    char* gu = reinterpret_cast<char*>(g_U) + (size_t)b * (II * 2048) +
               (size_t)i0 * 2048 + j * 64 + q * 16;

    int rd = 0, wr = NST - 1;
    for (int it = 0; it < UITER; it++) {
        cpwait<NST - 2>();  // stage rd resident
        __syncthreads();
        const char* sb = dsm + rd * STGB;

        // x[b][0:16] fp32 -> 4 LDS.128 (2-way bank, minor)
        u64 xr[8];
        {
            const float4* xp = reinterpret_cast<const float4*>(sb + 2048 + b * 64);
            #pragma unroll
            for (int k = 0; k < 4; k++) {
                float4 f = xp[k];
                const u64* pv = reinterpret_cast<const u64*>(&f);
                xr[2 * k] = pv[0];
                xr[2 * k + 1] = pv[1];
            }
        }
        float vv[8];
        #pragma unroll
        for (int dd = 0; dd < 8; dd++) {
            const float4* wp =
                reinterpret_cast<const float4*>(sb + (q * 8 + dd) * 64);
            u64 a0 = 0ULL, a1 = 0ULL;
            #pragma unroll
            for (int k = 0; k < 4; k++) {
                float4 f = wp[k];
                const u64* pv = reinterpret_cast<const u64*>(&f);
                a0 = fma2(pv[0], xr[2 * k], a0);
                a1 = fma2(pv[1], xr[2 * k + 1], a1);
            }
            float v = hsum2(add2(a0, a1));
            s0[dd] += v;
            vv[dd] = v;
        }
        // pack 8 halves (d ascending) -> one STG.128
        uint4 o;
        o.x = cvtpack(vv[0], vv[1]);
        o.y = cvtpack(vv[2], vv[3]);
        o.z = cvtpack(vv[4], vv[5]);
        o.w = cvtpack(vv[6], vv[7]);
        *reinterpret_cast<uint4*>(gu + (size_t)it * 2048) = o;

        // refill slot wr (consumed last iteration); commit EVERY iteration
        {
            int s = it + NST - 1;
            if (s < UITER) {
                unsigned sb2 = sb0 + (unsigned)(wr * STGB);
                if (t < 128) {
                    cpasync16(sb2 + (unsigned)(t * 16),
                              Wg + (size_t)s * 2048 + t * 16);
                } else {
                    cpasync16(sb2 + (unsigned)(2048 + xg * 16),
                              Xg + ((size_t)xb0 * II + i0 + s) * 64 + xp0 * 16);
                    cpasync16(sb2 + (unsigned)(2048 + xg * 16 + 16),
                              Xg + ((size_t)xb1 * II + i0 + s) * 64 + xp1 * 16);
                }
            }
            cpcommit();
        }
        if (++rd == NST) rd = 0;
        if (++wr == NST) wr = 0;
    }

    // s0 partial for this itile (single writer per element -> deterministic)
    #pragma unroll
    for (int dd = 0; dd < 8; dd++)
        g_spart[itile][b * (JJ * DD) + j * DD + q * 8 + dd] = s0[dd] * 0.03125f;
}

// ---------------------------------------------------------------------------
// Route compute step: lane l chunk m (uint4 = 8 halfs) holds j = 8m + (l>>2),
// d-seg (l&3)*8..+7. (Round-13 proven, unchanged.)
// ---------------------------------------------------------------------------
__device__ __forceinline__ void cvt8(const uint4& r, float* uf) {
    const __half2* h = reinterpret_cast<const __half2*>(&r);
    #pragma unroll
    for (int p = 0; p < 4; p++) {
        float2 f = __half22float2(h[p]);
        uf[2 * p] = f.x;
        uf[2 * p + 1] = f.y;
    }
}

__device__ __forceinline__ void route_step(const uint4* r, const float ov[4][8],
                                           float sacc[4][8]) {
    float uf[4][8];
    #pragma unroll
    for (int m = 0; m < 4; m++) cvt8(r[m], uf[m]);
    float tp[4];
    #pragma unroll
    for (int m = 0; m < 4; m++) {
        float a = uf[m][0] * ov[m][0];
        #pragma unroll
        for (int k = 1; k < 8; k++) a = fmaf(uf[m][k], ov[m][k], a);
        tp[m] = a;
    }
    #pragma unroll
    for (int s = 1; s < 4; s <<= 1)
        #pragma unroll
        for (int m = 0; m < 4; m++)
            tp[m] += __shfl_xor_sync(0xffffffffu, tp[m], s);
    float e[4], ss = 0.f;
    #pragma unroll
    for (int m = 0; m < 4; m++) {
        e[m] = __expf(tp[m]);
        ss += e[m];
    }
    ss += __shfl_xor_sync(0xffffffffu, ss, 4);
    ss += __shfl_xor_sync(0xffffffffu, ss, 8);
    ss += __shfl_xor_sync(0xffffffffu, ss, 16);
    float inv = __fdividef(1.0f, ss);
    float c[4];
    #pragma unroll
    for (int m = 0; m < 4; m++) c[m] = e[m] * inv;
    #pragma unroll
    for (int m = 0; m < 4; m++)
        #pragma unroll
        for (int k = 0; k < 8; k++) sacc[m][k] = fmaf(c[m], uf[m][k], sacc[m][k]);
}

// ---------------------------------------------------------------------------
// Kernel B: softmax routing pass, 5-stage block-wide cp.async ring, one
// barrier per iteration. (Round-13 proven, unchanged.)
// ---------------------------------------------------------------------------
template <int DIR>
__global__ void __launch_bounds__(256, 2) route_kernel() {
    extern __shared__ __align__(16) char dsm[];
    __half* sU = reinterpret_cast<__half*>(dsm);                  // NSTAGE*16KB
    float* sS = reinterpret_cast<float*>(dsm + NSTAGE * 16384);   // 8*1024 f

    const int itile = DIR ? (NTILE - 1 - (int)blockIdx.x) : (int)blockIdx.x;
    const int b = DIR ? (BB - 1 - (int)blockIdx.y) : (int)blockIdx.y;
    const int t = threadIdx.x, w = t >> 5, l = t & 31;

    float ov[4][8];
    {
        const float4* op = reinterpret_cast<const float4*>(g_osum + b * (JJ * DD));
        #pragma unroll
        for (int m = 0; m < 4; m++) {
            float4 f0 = op[m * 64 + 2 * l], f1 = op[m * 64 + 2 * l + 1];
            ov[m][0] = f0.x; ov[m][1] = f0.y; ov[m][2] = f0.z; ov[m][3] = f0.w;
            ov[m][4] = f1.x; ov[m][5] = f1.y; ov[m][6] = f1.z; ov[m][7] = f1.w;
        }
    }
    float sacc[4][8];
    #pragma unroll
    for (int m = 0; m < 4; m++)
        #pragma unroll
        for (int k = 0; k < 8; k++) sacc[m][k] = 0.f;

    const char* gbt = reinterpret_cast<const char*>(g_U) +
                      ((size_t)b * II + itile * 128) * 2048 + (size_t)t * 16;
    const unsigned su_base =
        (unsigned)__cvta_generic_to_shared(sU) + (unsigned)(t * 16);

    #pragma unroll
    for (int s = 0; s < NSTAGE - 1; s++) {
        #pragma unroll
        for (int k = 0; k < 4; k++)
            cpasync16(su_base + (unsigned)(s * 16384 + k * 4096),
                      gbt + (size_t)s * 16384 + k * 4096);
        cpcommit();
    }

    int rd = 0;
    int wr = NSTAGE - 1;
    for (int it = 0; it < NITER; it++) {
        cpwait<NSTAGE - 2>();
        __syncthreads();
        const uint4* p =
            reinterpret_cast<const uint4*>(sU + rd * 8192 + w * 1024);
        uint4 r[4];
        #pragma unroll
        for (int m = 0; m < 4; m++) r[m] = p[m * 32 + l];
        route_step(r, ov, sacc);
        {
            int s = it + NSTAGE - 1;
            if (s < NITER) {
                #pragma unroll
                for (int k = 0; k < 4; k++)
                    cpasync16(su_base + (unsigned)(wr * 16384 + k * 4096),
                              gbt + (size_t)s * 16384 + k * 4096);
            }
            cpcommit();
        }
        if (++rd == NSTAGE) rd = 0;
        if (++wr == NSTAGE) wr = 0;
    }
    __syncthreads();

    float4* sp = reinterpret_cast<float4*>(sS + w * 1024);
    #pragma unroll
    for (int m = 0; m < 4; m++) {
        sp[(m * 32 + l) * 2 + 0] =
            make_float4(sacc[m][0], sacc[m][1], sacc[m][2], sacc[m][3]);
        sp[(m * 32 + l) * 2 + 1] =
            make_float4(sacc[m][4], sacc[m][5], sacc[m][6], sacc[m][7]);
    }
    __syncthreads();
    for (int idx = t; idx < JJ * DD; idx += 256) {
        float v = 0.f;
        #pragma unroll
        for (int ww = 0; ww < 8; ww++) v += sS[ww * 1024 + idx];
        g_spart[itile][b * (JJ * DD) + idx] = v;
    }
}

// ---------------------------------------------------------------------------
// Kernel C: reduce itile partials, squash, update osum / write final out.
// mode 0: osum = o ; mode 1: osum += o ; mode 2: out = o.
// ---------------------------------------------------------------------------
__global__ void __launch_bounds__(256) squash_kernel(float* __restrict__ out,
                                                     int mode) {
    const int t = threadIdx.x;
    const int bj = blockIdx.x * 8 + (t >> 5);
    const int l = t & 31;
    float v = 0.f;
    #pragma unroll
    for (int it = 0; it < NTILE; it++) v += g_spart[it][bj * DD + l];
    float s2 = v * v;
    #pragma unroll
    for (int s = 1; s < 32; s <<= 1) s2 += __shfl_xor_sync(0xffffffffu, s2, s);
    float scale = (s2 / (1.0f + s2)) * rsqrtf(s2 + 1e-7f);
    float o = scale * v;
    if (mode == 2)
        out[bj * DD + l] = o;
    else if (mode == 1)
        g_osum[bj * DD + l] += o;
    else
        g_osum[bj * DD + l] = o;
}

// ---------------------------------------------------------------------------
extern "C" void kernel_launch(void* const* d_in, const int* in_sizes, int n_in,
                              void* d_out, int out_size) {
    const float* x;
    const float* W;
    if (in_sizes[0] == BB * II * CC) {
        x = (const float*)d_in[0];
        W = (const float*)d_in[1];
    } else {
        x = (const float*)d_in[1];
        W = (const float*)d_in[0];
    }

    const int uhat_smem = NST * STGB;                                      // 49152
    const int route_smem = NSTAGE * 16384 + 8 * 1024 * (int)sizeof(float); // 114688
    cudaFuncSetAttribute(uhat_kernel, cudaFuncAttributeMaxDynamicSharedMemorySize,
                         uhat_smem);
    cudaFuncSetAttribute(route_kernel<0>,
                         cudaFuncAttributeMaxDynamicSharedMemorySize, route_smem);
    cudaFuncSetAttribute(route_kernel<1>,
                         cudaFuncAttributeMaxDynamicSharedMemorySize, route_smem);

    float* out = (float*)d_out;
    uhat_kernel<<<dim3(JJ, NTILE), 256, uhat_smem>>>(x, W);
    squash_kernel<<<BB * JJ / 8, 256>>>(out, 0);
    route_kernel<0><<<dim3(NTILE, BB), 256, route_smem>>>();
    squash_kernel<<<BB * JJ / 8, 256>>>(out, 1);
    route_kernel<1><<<dim3(NTILE, BB), 256, route_smem>>>();
    squash_kernel<<<BB * JJ / 8, 256>>>(out, 2);
}